// round 11
// baseline (speedup 1.0000x reference)
#include <cuda_runtime.h>
#include <math.h>

#define Nn 16384
#define Dd 128
#define Cc 10
#define Kk 16
#define SLB 44
#define NB2 (SLB * Cc)            // 440 blocks for kernel B (~3/SM)
#define EPSf 1.1920928955078125e-7f
#define LOG2PIf 1.8378770664093453f
#define LN2f 0.6931471805599453f

// static scratch (no allocation); g_sum/g_cnt/g_done zero-initial, reset by
// kernel B's winner block each run so graph replays are self-contained.
__device__ float    g_inv[Cc * Kk * Dd];
__device__ float    g_nm [Cc * Kk * Dd];   // pre-negated m2 = -mu/scale
__device__ float    g_pre[Cc * Kk];
__device__ float    g_sum[Cc];
__device__ int      g_cnt[Cc];
__device__ int      g_rows[Cc * Nn];
__device__ unsigned g_done;

typedef unsigned long long u64;

__device__ __forceinline__ float softplusf(float x) {
    return fmaxf(x, 0.0f) + log1pf(expf(-fabsf(x)));
}

// packed f32x2 helpers (sm_100a): a u64 carries two packed floats (lo,hi).
__device__ __forceinline__ u64 fma2(u64 a, u64 b, u64 c) {
    u64 r; asm("fma.rn.f32x2 %0,%1,%2,%3;" : "=l"(r) : "l"(a), "l"(b), "l"(c)); return r;
}
__device__ __forceinline__ u64 mul2(u64 a, u64 b) {
    u64 r; asm("mul.rn.f32x2 %0,%1,%2;" : "=l"(r) : "l"(a), "l"(b)); return r;
}
__device__ __forceinline__ void upk2(u64 d, float& lo, float& hi) {
    asm("mov.b64 {%0,%1},%2;" : "=f"(lo), "=f"(hi) : "l"(d));
}

// ================= Kernel A: bucket + prep (once, in parallel) ===============
// grid 64 x 256. Bucketing: one row/thread. Prep: warps 0..159 do one (c,k).
__global__ void __launch_bounds__(256)
prep_bucket_kernel(const int* __restrict__ y,
                   const float* __restrict__ mu,
                   const float* __restrict__ lower,
                   const float* __restrict__ upper,
                   const float* __restrict__ sigma) {
    __shared__ int s_cnt[Cc];
    __shared__ int s_off[Cc];
    int t    = threadIdx.x;
    int lane = t & 31;
    int w8   = t >> 5;

    // bucket
    int n0 = blockIdx.x * 256 + t;
    int c_row;
    if (t < Cc) s_cnt[t] = 0;
    __syncthreads();
    c_row = y[n0];
    atomicAdd(&s_cnt[c_row], 1);
    __syncthreads();
    if (t < Cc) { s_off[t] = atomicAdd(&g_cnt[t], s_cnt[t]); s_cnt[t] = 0; }
    __syncthreads();
    {
        int p = atomicAdd(&s_cnt[c_row], 1);
        g_rows[c_row * Nn + s_off[c_row] + p] = n0;
    }

    // prep (one warp per (c,k))
    int w = blockIdx.x * 8 + w8;
    if (w < Cc * Kk) {
        int base = w * Dd + lane * 4;
        float4 m4 = *(const float4*)(mu    + base);
        float4 l4 = *(const float4*)(lower + base);
        float4 u4 = *(const float4*)(upper + base);
        float4 s4 = *(const float4*)(sigma + base);
        float mv[4] = {m4.x, m4.y, m4.z, m4.w};
        float lv[4] = {l4.x, l4.y, l4.z, l4.w};
        float uv[4] = {u4.x, u4.y, u4.z, u4.w};
        float sv[4] = {s4.x, s4.y, s4.z, s4.w};
        float invv[4], nmv[4];
        float prod = 1.0f, slog = 0.0f;
#pragma unroll
        for (int j = 0; j < 4; j++) {
            float scale = EPSf + softplusf(sv[j]);
            float inv   = 1.0f / scale;
            float z = normcdff((uv[j] - mv[j]) * inv) - normcdff((lv[j] - mv[j]) * inv);
            prod *= z;
            slog += logf(scale);
            invv[j] = inv;
            nmv[j]  = -mv[j] * inv;
        }
        *(float4*)(g_inv + base) = make_float4(invv[0], invv[1], invv[2], invv[3]);
        *(float4*)(g_nm  + base) = make_float4(nmv[0],  nmv[1],  nmv[2],  nmv[3]);
#pragma unroll
        for (int o = 16; o > 0; o >>= 1) {
            prod *= __shfl_xor_sync(0xffffffffu, prod, o);
            slog += __shfl_xor_sync(0xffffffffu, slog, o);
        }
        if (lane == 0)
            g_pre[w] = -logf(prod + EPSf) - slog;   // -log_norm - sum(log scale)
    }
}

// ================= Kernel B: main compute ====================================
// grid 440 x 256 (3 blocks/SM). Block = (class c, slice), ~37 rows each.
__global__ void __launch_bounds__(256, 3)
main_kernel(const float* __restrict__ X,
            const float* __restrict__ resp,
            const float* __restrict__ lower, const float* __restrict__ upper,
            const float* __restrict__ logits_k,
            const float* __restrict__ eta_p,
            float* __restrict__ out) {
    __shared__ float4 s_iv[Kk * 32];   // 8 KB: class inv (k-major, lane float4)
    __shared__ float4 s_nm[Kk * 32];   // 8 KB: class -m2
    __shared__ float  s_b2[Kk];        // -2*base for this class
    __shared__ float  s_wsum[8];
    __shared__ bool   s_last;

    int t    = threadIdx.x;
    int lane = t & 31;
    int w8   = t >> 5;
    int c     = blockIdx.x % Cc;
    int slice = blockIdx.x / Cc;
    float eta = *eta_p;

    // warp 0: b2[k] = -2*base
    if (t < 32) {
        int kk = t & 15;
        float lg = logits_k[c * Kk + kk];
        float m = lg;
#pragma unroll
        for (int o = 8; o > 0; o >>= 1)
            m = fmaxf(m, __shfl_xor_sync(0xffffffffu, m, o, 16));
        float se = expf(lg - m);
#pragma unroll
        for (int o = 8; o > 0; o >>= 1)
            se += __shfl_xor_sync(0xffffffffu, se, o, 16);
        float log_cat = lg - (m + logf(se));
        float etac = (eta == 0.0f) ? (-2.0f * Dd * LN2f) : 0.0f;
        if (t < Kk)
            s_b2[t] = -2.0f * (log_cat + g_pre[c * Kk + kk] - 0.5f * Dd * LOG2PIf + etac);
    }

    // all threads: fill smem weights (L2-hot after kernel A)
    {
        const float4* gi = (const float4*)g_inv + (size_t)c * (Kk * 32);
        const float4* gm = (const float4*)g_nm  + (size_t)c * (Kk * 32);
#pragma unroll
        for (int i = 0; i < 2; i++) {
            int idx = t + i * 256;
            s_iv[idx] = gi[idx];
            s_nm[idx] = gm[idx];
        }
    }
    __syncthreads();

    // row range for this block / warp
    int cnt   = g_cnt[c];
    int start = (int)(((long)slice       * cnt) / SLB);
    int end   = (int)(((long)(slice + 1) * cnt) / SLB);
    int len = end - start;
    int ws  = start + (len * w8)       / 8;
    int we  = start + (len * (w8 + 1)) / 8;

    const int* rowlist = g_rows + (size_t)c * Nn;
    const ulonglong2* s_ivd = (const ulonglong2*)s_iv;
    const ulonglong2* s_nmd = (const ulonglong2*)s_nm;
    float acc = 0.0f;

    if (eta == 0.0f) {
        if (ws < we) {
            int nn[4]; ulonglong2 xn[4]; float rn[4];
#pragma unroll
            for (int rr = 0; rr < 4; rr++) nn[rr] = rowlist[min(ws + rr, we - 1)];
#pragma unroll
            for (int rr = 0; rr < 4; rr++)
                xn[rr] = *(const ulonglong2*)(X + (size_t)nn[rr] * Dd + lane * 4);
#pragma unroll
            for (int rr = 0; rr < 4; rr++)
                rn[rr] = (lane < Kk && ws + rr < we)
                       ? -0.5f * __ldg(resp + ((size_t)c * Nn + nn[rr]) * Kk + lane)
                       : 0.0f;

            for (int p = ws; p < we; p += 4) {
                ulonglong2 xc[4]; float rc[4];
#pragma unroll
                for (int rr = 0; rr < 4; rr++) { xc[rr] = xn[rr]; rc[rr] = rn[rr]; }

                int p2 = p + 4;
                if (p2 < we) {
#pragma unroll
                    for (int rr = 0; rr < 4; rr++) nn[rr] = rowlist[min(p2 + rr, we - 1)];
#pragma unroll
                    for (int rr = 0; rr < 4; rr++)
                        xn[rr] = *(const ulonglong2*)(X + (size_t)nn[rr] * Dd + lane * 4);
#pragma unroll
                    for (int rr = 0; rr < 4; rr++)
                        rn[rr] = (lane < Kk && p2 + rr < we)
                               ? -0.5f * __ldg(resp + ((size_t)c * Nn + nn[rr]) * Kk + lane)
                               : 0.0f;
                }

                float tl[4];
#pragma unroll
                for (int rr = 0; rr < 4; rr++)
                    tl[rr] = (lane < Kk) ? rc[rr] * s_b2[lane] : 0.0f;

#pragma unroll
                for (int k = 0; k < Kk; k++) {
                    ulonglong2 iv = s_ivd[k * 32 + lane];
                    ulonglong2 nm = s_nmd[k * 32 + lane];
#pragma unroll
                    for (int rr = 0; rr < 4; rr++) {
                        float rh = __shfl_sync(0xffffffffu, rc[rr], k);
                        u64 z01 = fma2(xc[rr].x, iv.x, nm.x);
                        u64 z23 = fma2(xc[rr].y, iv.y, nm.y);
                        u64 sp  = fma2(z01, z01, mul2(z23, z23));
                        float slo, shi; upk2(sp, slo, shi);
                        tl[rr] = fmaf(rh, slo + shi, tl[rr]);   // rh = -0.5*r
                    }
                }
                acc += (tl[0] + tl[1]) + (tl[2] + tl[3]);
            }
        }
    } else {
        // general path (eta != 0); s_nm holds NEGATED m2
        for (int pos = ws; pos < we; pos++) {
            int n = rowlist[pos];
            float4 xv = *(const float4*)(X + (size_t)n * Dd + lane * 4);
            float respl = (lane < Kk)
                        ? __ldg(resp + ((size_t)c * Nn + n) * Kk + lane) : 0.0f;
            float tl = (lane < Kk) ? respl * (-0.5f * s_b2[lane]) : 0.0f;
            const float4* lp = (const float4*)lower + (size_t)c * Kk * 32 + lane;
            const float4* up = (const float4*)upper + (size_t)c * Kk * 32 + lane;
#pragma unroll
            for (int k = 0; k < Kk; k++) {
                float4 iv = s_iv[k * 32 + lane];
                float4 nm = s_nm[k * 32 + lane];
                float4 lo = lp[k * 32];
                float4 uu = up[k * 32];
                float z0 = fmaf(xv.x, iv.x, nm.x);
                float z1 = fmaf(xv.y, iv.y, nm.y);
                float z2 = fmaf(xv.z, iv.z, nm.z);
                float z3 = fmaf(xv.w, iv.w, nm.w);
                float sq = fmaf(z0, z0, fmaf(z1, z1, fmaf(z2, z2, z3 * z3)));
                float q  = softplusf(-eta * (xv.x - lo.x)) + softplusf(-eta * (uu.x - xv.x))
                         + softplusf(-eta * (xv.y - lo.y)) + softplusf(-eta * (uu.y - xv.y))
                         + softplusf(-eta * (xv.z - lo.z)) + softplusf(-eta * (uu.z - xv.z))
                         + softplusf(-eta * (xv.w - lo.w)) + softplusf(-eta * (uu.w - xv.w));
                float r  = __shfl_sync(0xffffffffu, respl, k);
                tl -= r * fmaf(0.5f, sq, q);
            }
            acc += tl;
        }
    }

    // block reduce -> one atomic per block
#pragma unroll
    for (int o = 16; o > 0; o >>= 1)
        acc += __shfl_xor_sync(0xffffffffu, acc, o);
    if (lane == 0) s_wsum[w8] = acc;
    __syncthreads();
    if (t == 0) {
        float b = ((s_wsum[0] + s_wsum[1]) + (s_wsum[2] + s_wsum[3]))
                + ((s_wsum[4] + s_wsum[5]) + (s_wsum[6] + s_wsum[7]));
        atomicAdd(&g_sum[c], b);
    }

    // last block: final reduce + state reset (g_cnt reset AFTER use; every
    // block has already read g_cnt before incrementing g_done)
    __threadfence();
    __syncthreads();
    if (t == 0) {
        unsigned d = atomicAdd(&g_done, 1u);
        s_last = (d == (unsigned)(NB2 - 1));
    }
    __syncthreads();
    if (s_last) {
        __threadfence();
        if (t < 32) {
            double v = 0.0;
            if (t < Cc) {
                int cn = g_cnt[t];
                if (cn > 0) v = (double)g_sum[t] / ((double)cn * (double)Kk);
            }
#pragma unroll
            for (int o = 16; o > 0; o >>= 1)
                v += __shfl_xor_sync(0xffffffffu, v, o);
            if (t == 0) out[0] = (float)(-v);
            if (t < Cc) { g_sum[t] = 0.0f; g_cnt[t] = 0; }
            if (t == 0) g_done = 0u;
        }
    }
}

extern "C" void kernel_launch(void* const* d_in, const int* in_sizes, int n_in,
                              void* d_out, int out_size) {
    const float* X      = (const float*)d_in[0];
    const int*   y      = (const int*)  d_in[1];
    const float* resp   = (const float*)d_in[2];
    const float* mu     = (const float*)d_in[3];
    const float* lower  = (const float*)d_in[4];
    const float* upper  = (const float*)d_in[5];
    const float* sigma  = (const float*)d_in[6];
    const float* logits = (const float*)d_in[7];
    const float* eta    = (const float*)d_in[8];
    float* out = (float*)d_out;

    prep_bucket_kernel<<<64, 256>>>(y, mu, lower, upper, sigma);
    main_kernel<<<NB2, 256>>>(X, resp, lower, upper, logits, eta, out);
}

// round 12
// speedup vs baseline: 1.1625x; 1.1625x over previous
#include <cuda_runtime.h>
#include <math.h>

#define Nn 16384
#define Dd 128
#define Cc 10
#define Kk 16
#define SLICES 29
#define NB (SLICES * Cc)          // 290 blocks; 2/SM guaranteed -> co-resident
#define EPSf 1.1920928955078125e-7f
#define LOG2PIf 1.8378770664093453f
#define LN2f 0.6931471805599453f

// static scratch (no allocation); all-zero initial state, restored at end of
// every run by the winner block so graph replays are self-contained.
__device__ float    g_inv[Cc * Kk * Dd];
__device__ float    g_nm [Cc * Kk * Dd];   // pre-negated: -mu/scale
__device__ float    g_pre[Cc * Kk];
__device__ float    g_sum[Cc];
__device__ int      g_cnt[Cc];
__device__ int      g_rows[Cc * Nn];
__device__ unsigned g_bar;
__device__ unsigned g_done;

typedef unsigned long long u64;

__device__ __forceinline__ float softplus_fast(float x) {
    return fmaxf(x, 0.0f) + __logf(1.0f + __expf(-fabsf(x)));
}
__device__ __forceinline__ float softplusf(float x) {   // precise (eta path)
    return fmaxf(x, 0.0f) + log1pf(expf(-fabsf(x)));
}

// packed f32x2 helpers (sm_100a): a u64 carries two packed floats (lo,hi).
__device__ __forceinline__ u64 fma2(u64 a, u64 b, u64 c) {
    u64 r; asm("fma.rn.f32x2 %0,%1,%2,%3;" : "=l"(r) : "l"(a), "l"(b), "l"(c)); return r;
}
__device__ __forceinline__ u64 mul2(u64 a, u64 b) {
    u64 r; asm("mul.rn.f32x2 %0,%1,%2;" : "=l"(r) : "l"(a), "l"(b)); return r;
}
__device__ __forceinline__ void upk2(u64 d, float& lo, float& hi) {
    asm("mov.b64 {%0,%1},%2;" : "=f"(lo), "=f"(hi) : "l"(d));
}

__global__ void __launch_bounds__(256, 2)
fused_kernel(const float* __restrict__ X, const int* __restrict__ y,
             const float* __restrict__ resp,
             const float* __restrict__ mu,
             const float* __restrict__ lower, const float* __restrict__ upper,
             const float* __restrict__ sigma,
             const float* __restrict__ logits_k,
             const float* __restrict__ eta_p,
             float* __restrict__ out) {
    __shared__ float4 s_iv[Kk * 32];     // 8 KB: class inv  (k-major, lane float4)
    __shared__ float4 s_nm[Kk * 32];     // 8 KB: class -m2  (already negated)
    __shared__ int    s_cnt[Cc];
    __shared__ int    s_off[Cc];
    __shared__ float  s_b2[Kk];          // -2*base for this block's class
    __shared__ float  s_wsum[8];
    __shared__ bool   s_last;

    int t    = threadIdx.x;
    int lane = t & 31;
    int w8   = t >> 5;
    float eta = *eta_p;

    // ---------------- Phase A1: bucket rows (ALL blocks, ~57 rows each) ------
    int bs = (int)(((long)blockIdx.x       * Nn) / NB);
    int be = (int)(((long)(blockIdx.x + 1) * Nn) / NB);
    int n0 = bs + t;
    int c_row = -1;
    if (t < Cc) s_cnt[t] = 0;
    __syncthreads();
    if (n0 < be) { c_row = y[n0]; atomicAdd(&s_cnt[c_row], 1); }
    __syncthreads();
    if (t < Cc) { s_off[t] = atomicAdd(&g_cnt[t], s_cnt[t]); s_cnt[t] = 0; }
    __syncthreads();
    if (n0 < be) {
        int p = atomicAdd(&s_cnt[c_row], 1);
        g_rows[c_row * Nn + s_off[c_row] + p] = n0;
    }

    // ---------------- Phase A2: per-(c,k) precompute (warps 0..159, fast) ----
    int w = blockIdx.x * 8 + w8;
    if (w < Cc * Kk) {
        int base = w * Dd + lane * 4;
        float4 m4 = *(const float4*)(mu    + base);
        float4 l4 = *(const float4*)(lower + base);
        float4 u4 = *(const float4*)(upper + base);
        float4 s4 = *(const float4*)(sigma + base);
        float mv[4] = {m4.x, m4.y, m4.z, m4.w};
        float lv[4] = {l4.x, l4.y, l4.z, l4.w};
        float uv[4] = {u4.x, u4.y, u4.z, u4.w};
        float sv[4] = {s4.x, s4.y, s4.z, s4.w};
        float invv[4], nmv[4];
        float prod = 1.0f, slog = 0.0f;
#pragma unroll
        for (int j = 0; j < 4; j++) {
            float scale = EPSf + softplus_fast(sv[j]);
            float inv   = __fdividef(1.0f, scale);
            float z = normcdff((uv[j] - mv[j]) * inv) - normcdff((lv[j] - mv[j]) * inv);
            prod *= z;
            slog += __logf(scale);
            invv[j] = inv;
            nmv[j]  = -mv[j] * inv;
        }
        *(float4*)(g_inv + base) = make_float4(invv[0], invv[1], invv[2], invv[3]);
        *(float4*)(g_nm  + base) = make_float4(nmv[0],  nmv[1],  nmv[2],  nmv[3]);
#pragma unroll
        for (int o = 16; o > 0; o >>= 1) {
            prod *= __shfl_xor_sync(0xffffffffu, prod, o);
            slog += __shfl_xor_sync(0xffffffffu, slog, o);
        }
        if (lane == 0)
            g_pre[w] = -__logf(prod + EPSf) - slog;  // -log_norm - sum(log scale)
    }

    // ---------------- grid barrier (290 blocks, 2/SM guaranteed) -------------
    __syncthreads();
    if (t == 0) {
        __threadfence();
        atomicAdd(&g_bar, 1u);
        while (*(volatile unsigned*)&g_bar < (unsigned)NB) { __nanosleep(32); }
        __threadfence();
    }
    __syncthreads();

    // ---------------- this block's class + smem weights ----------------------
    int c     = blockIdx.x % Cc;
    int slice = blockIdx.x / Cc;

    {   // cooperative fill (g_nm already negated)
        const float4* gi = (const float4*)g_inv + (size_t)c * (Kk * 32);
        const float4* gm = (const float4*)g_nm  + (size_t)c * (Kk * 32);
#pragma unroll
        for (int i = 0; i < 2; i++) {
            int idx = t + i * 256;
            s_iv[idx] = gi[idx];
            s_nm[idx] = gm[idx];
        }
    }

    // b2[k] = -2*base for class c (warp 0, fast intrinsics)
    if (t < 32) {
        int kk = t & 15;
        float lg = logits_k[c * Kk + kk];
        float m = lg;
#pragma unroll
        for (int o = 8; o > 0; o >>= 1)
            m = fmaxf(m, __shfl_xor_sync(0xffffffffu, m, o, 16));
        float se = __expf(lg - m);
#pragma unroll
        for (int o = 8; o > 0; o >>= 1)
            se += __shfl_xor_sync(0xffffffffu, se, o, 16);
        float log_cat = lg - (m + __logf(se));
        float etac = (eta == 0.0f) ? (-2.0f * Dd * LN2f) : 0.0f;
        if (t < Kk)
            s_b2[t] = -2.0f * (log_cat + g_pre[c * Kk + kk] - 0.5f * Dd * LOG2PIf + etac);
    }
    __syncthreads();

    // ---------------- Phase B: pipelined f32x2 main loop ---------------------
    int cnt   = g_cnt[c];
    int start = (int)(((long)slice       * cnt) / SLICES);
    int end   = (int)(((long)(slice + 1) * cnt) / SLICES);
    int len = end - start;
    int ws  = start + (len * w8)       / 8;
    int we  = start + (len * (w8 + 1)) / 8;

    const int* rowlist = g_rows + (size_t)c * Nn;
    const ulonglong2* s_ivd = (const ulonglong2*)s_iv;
    const ulonglong2* s_nmd = (const ulonglong2*)s_nm;
    float acc = 0.0f;

    if (eta == 0.0f) {
        if (ws < we) {
            int nn[4]; ulonglong2 xn[4]; float rn[4];
#pragma unroll
            for (int rr = 0; rr < 4; rr++) nn[rr] = rowlist[min(ws + rr, we - 1)];
#pragma unroll
            for (int rr = 0; rr < 4; rr++)
                xn[rr] = *(const ulonglong2*)(X + (size_t)nn[rr] * Dd + lane * 4);
#pragma unroll
            for (int rr = 0; rr < 4; rr++)
                rn[rr] = (lane < Kk && ws + rr < we)
                       ? -0.5f * __ldg(resp + ((size_t)c * Nn + nn[rr]) * Kk + lane)
                       : 0.0f;

            for (int p = ws; p < we; p += 4) {
                ulonglong2 xc[4]; float rc[4];
#pragma unroll
                for (int rr = 0; rr < 4; rr++) { xc[rr] = xn[rr]; rc[rr] = rn[rr]; }

                int p2 = p + 4;
                if (p2 < we) {
#pragma unroll
                    for (int rr = 0; rr < 4; rr++) nn[rr] = rowlist[min(p2 + rr, we - 1)];
#pragma unroll
                    for (int rr = 0; rr < 4; rr++)
                        xn[rr] = *(const ulonglong2*)(X + (size_t)nn[rr] * Dd + lane * 4);
#pragma unroll
                    for (int rr = 0; rr < 4; rr++)
                        rn[rr] = (lane < Kk && p2 + rr < we)
                               ? -0.5f * __ldg(resp + ((size_t)c * Nn + nn[rr]) * Kk + lane)
                               : 0.0f;
                }

                float tl[4];
#pragma unroll
                for (int rr = 0; rr < 4; rr++)
                    tl[rr] = (lane < Kk) ? rc[rr] * s_b2[lane] : 0.0f;

#pragma unroll
                for (int k = 0; k < Kk; k++) {
                    ulonglong2 iv = s_ivd[k * 32 + lane];
                    ulonglong2 nm = s_nmd[k * 32 + lane];
#pragma unroll
                    for (int rr = 0; rr < 4; rr++) {
                        float rh = __shfl_sync(0xffffffffu, rc[rr], k);
                        u64 z01 = fma2(xc[rr].x, iv.x, nm.x);
                        u64 z23 = fma2(xc[rr].y, iv.y, nm.y);
                        u64 sp  = fma2(z01, z01, mul2(z23, z23));
                        float slo, shi; upk2(sp, slo, shi);
                        tl[rr] = fmaf(rh, slo + shi, tl[rr]);   // rh = -0.5*r
                    }
                }
                acc += (tl[0] + tl[1]) + (tl[2] + tl[3]);
            }
        }
    } else {
        // general path (eta != 0); s_nm holds NEGATED m2
        for (int pos = ws; pos < we; pos++) {
            int n = rowlist[pos];
            float4 xv = *(const float4*)(X + (size_t)n * Dd + lane * 4);
            float respl = (lane < Kk)
                        ? __ldg(resp + ((size_t)c * Nn + n) * Kk + lane) : 0.0f;
            float tl = (lane < Kk) ? respl * (-0.5f * s_b2[lane]) : 0.0f;
            const float4* lp = (const float4*)lower + (size_t)c * Kk * 32 + lane;
            const float4* up = (const float4*)upper + (size_t)c * Kk * 32 + lane;
#pragma unroll
            for (int k = 0; k < Kk; k++) {
                float4 iv = s_iv[k * 32 + lane];
                float4 nm = s_nm[k * 32 + lane];
                float4 lo = lp[k * 32];
                float4 uu = up[k * 32];
                float z0 = fmaf(xv.x, iv.x, nm.x);
                float z1 = fmaf(xv.y, iv.y, nm.y);
                float z2 = fmaf(xv.z, iv.z, nm.z);
                float z3 = fmaf(xv.w, iv.w, nm.w);
                float sq = fmaf(z0, z0, fmaf(z1, z1, fmaf(z2, z2, z3 * z3)));
                float q  = softplusf(-eta * (xv.x - lo.x)) + softplusf(-eta * (uu.x - xv.x))
                         + softplusf(-eta * (xv.y - lo.y)) + softplusf(-eta * (uu.y - xv.y))
                         + softplusf(-eta * (xv.z - lo.z)) + softplusf(-eta * (uu.z - xv.z))
                         + softplusf(-eta * (xv.w - lo.w)) + softplusf(-eta * (uu.w - xv.w));
                float r  = __shfl_sync(0xffffffffu, respl, k);
                tl -= r * fmaf(0.5f, sq, q);
            }
            acc += tl;
        }
    }

    // block reduce -> one atomic per block
#pragma unroll
    for (int o = 16; o > 0; o >>= 1)
        acc += __shfl_xor_sync(0xffffffffu, acc, o);
    if (lane == 0) s_wsum[w8] = acc;
    __syncthreads();
    if (t == 0) {
        float b = ((s_wsum[0] + s_wsum[1]) + (s_wsum[2] + s_wsum[3]))
                + ((s_wsum[4] + s_wsum[5]) + (s_wsum[6] + s_wsum[7]));
        atomicAdd(&g_sum[c], b);
    }

    // ---------------- last block: final reduce + state reset ------------------
    __threadfence();
    __syncthreads();
    if (t == 0) {
        unsigned d = atomicAdd(&g_done, 1u);
        s_last = (d == (unsigned)(NB - 1));
    }
    __syncthreads();
    if (s_last) {
        __threadfence();
        if (t < 32) {
            double v = 0.0;
            if (t < Cc) {
                int cn = g_cnt[t];
                if (cn > 0) v = (double)g_sum[t] / ((double)cn * (double)Kk);
            }
#pragma unroll
            for (int o = 16; o > 0; o >>= 1)
                v += __shfl_xor_sync(0xffffffffu, v, o);
            if (t == 0) out[0] = (float)(-v);
            // reset state for next graph replay
            if (t < Cc) { g_sum[t] = 0.0f; g_cnt[t] = 0; }
            if (t == 0) { g_bar = 0u; g_done = 0u; }
        }
    }
}

extern "C" void kernel_launch(void* const* d_in, const int* in_sizes, int n_in,
                              void* d_out, int out_size) {
    const float* X      = (const float*)d_in[0];
    const int*   y      = (const int*)  d_in[1];
    const float* resp   = (const float*)d_in[2];
    const float* mu     = (const float*)d_in[3];
    const float* lower  = (const float*)d_in[4];
    const float* upper  = (const float*)d_in[5];
    const float* sigma  = (const float*)d_in[6];
    const float* logits = (const float*)d_in[7];
    const float* eta    = (const float*)d_in[8];
    float* out = (float*)d_out;

    fused_kernel<<<NB, 256>>>(X, y, resp, mu, lower, upper, sigma, logits, eta, out);
}